// round 11
// baseline (speedup 1.0000x reference)
#include <cuda_runtime.h>
#include <cuda_fp16.h>
#include <cstdint>

// ============================================================================
// MoEConv implicit GEMM on mma.sync fp16 (single term, fp32 acc)
// R10: warp tile 64x64 (8 warps, 256 thr), CTA 256px x 128co, 3-stage W pipe.
// x[32,64,64,64] f32, idx[32] i32, Wc[4,128,64,3,3] f32, bc[4,128] f32
// out[32,128,64,64] f32
// ============================================================================

#define HW_    64
#define B_     32
#define OUT_C  128
#define IN_C   64

// ---- device scratch (allocation-free) ----
__device__ __align__(128) __half g_xt[(size_t)B_*HW_*HW_*IN_C];  // [b][h][w][ci]
__device__ __align__(128) __half g_wt[(size_t)4*9*OUT_C*IN_C];   // [e][k][co][ci]

__device__ __forceinline__ uint32_t smem_u32(const void* p) {
    uint32_t a;
    asm("{ .reg .u64 t; cvta.to.shared.u64 t, %1; cvt.u32.u64 %0, t; }" : "=r"(a) : "l"(p));
    return a;
}

#define CP_ASYNC(dst, src, sz) \
    asm volatile("cp.async.cg.shared.global [%0], [%1], 16, %2;" :: "r"(dst), "l"(src), "r"(sz) : "memory")
#define CP_COMMIT() asm volatile("cp.async.commit_group;" ::: "memory")
#define CP_WAIT1()  asm volatile("cp.async.wait_group 1;" ::: "memory")

#define LDSM_X4(r0,r1,r2,r3,a) \
    asm volatile("ldmatrix.sync.aligned.m8n8.x4.shared.b16 {%0,%1,%2,%3},[%4];" \
        : "=r"(r0),"=r"(r1),"=r"(r2),"=r"(r3) : "r"(a))

#define HMMA(c0,c1,c2,c3,a0,a1,a2,a3,b0,b1) \
    asm volatile("mma.sync.aligned.m16n8k16.row.col.f32.f16.f16.f32 " \
        "{%0,%1,%2,%3},{%4,%5,%6,%7},{%8,%9},{%0,%1,%2,%3};" \
        : "+f"(c0),"+f"(c1),"+f"(c2),"+f"(c3) \
        : "r"(a0),"r"(a1),"r"(a2),"r"(a3),"r"(b0),"r"(b1))

// ============================================================================
// Kernel 0: weights f32 -> fp16, layout [e][k][co][ci]
// ============================================================================
__global__ void prep_w(const float* __restrict__ Wc)
{
    int id = blockIdx.x * 256 + threadIdx.x;            // (e*128+co)*64+ci
    if (id >= 4 * OUT_C * IN_C) return;
    const float* src = Wc + (size_t)id * 9;
    int e   = id >> 13;
    int rem = id & 8191;
    #pragma unroll
    for (int k = 0; k < 9; ++k)
        g_wt[(size_t)(e * 9 + k) * 8192 + rem] = __float2half_rn(src[k]);
}

// ============================================================================
// Kernel 1: x [b][ci][h][w] f32 -> Xt [b][h][w][ci] fp16
// ============================================================================
__global__ void prep_x(const float* __restrict__ x)
{
    __shared__ float s[IN_C * 65];
    const int h = blockIdx.x, b = blockIdx.y, t = threadIdx.x;  // 256 threads
    {
        int ci = t >> 2, w4 = t & 3;
        const float* src = x + (((size_t)b * IN_C + ci) * HW_ + h) * HW_;
        #pragma unroll
        for (int q = 0; q < 4; ++q) {
            int w = (w4 + q * 4) * 4;
            float4 v = *(const float4*)(src + w);
            s[ci * 65 + w + 0] = v.x; s[ci * 65 + w + 1] = v.y;
            s[ci * 65 + w + 2] = v.z; s[ci * 65 + w + 3] = v.w;
        }
    }
    __syncthreads();
    {
        int w = t & 63, ci0 = (t >> 6) * 16;
        uint32_t pk[8];
        #pragma unroll
        for (int j = 0; j < 8; ++j) {
            __half h0 = __float2half_rn(s[(ci0 + 2*j    ) * 65 + w]);
            __half h1 = __float2half_rn(s[(ci0 + 2*j + 1) * 65 + w]);
            pk[j] = ((uint32_t)__half_as_ushort(h1) << 16) | __half_as_ushort(h0);
        }
        size_t base = (((size_t)b * HW_ + h) * HW_ + w) * IN_C + ci0;
        *(uint4*)(g_xt + base)     = make_uint4(pk[0], pk[1], pk[2], pk[3]);
        *(uint4*)(g_xt + base + 8) = make_uint4(pk[4], pk[5], pk[6], pk[7]);
    }
}

// ============================================================================
// Main kernel: CTA = (4 image rows = 256 px, sample). 256 threads = 8 warps
// (4m x 2n). Warp tile 64(px) x 64(co). K = 64/tap, 9 taps, fp16.
// SMEM: X halo [6][66][72 pitch] + W [128co][72] x3 bufs (wait_group 1).
// ============================================================================
#define XPITCH  72
#define XROWB   144
#define XSZ     (6 * 66 * XROWB)         // 57,024 B
#define WSZ     (OUT_C * XROWB)          // 18,432 B
#define SM_X    0
#define SM_W    XSZ
#define SMEM_SZ (XSZ + 3 * WSZ)          // 112,320 B

__device__ __forceinline__ void load_w_tile(uint32_t wbuf_s, int e, int k, int tid)
{
    // 128 co x 8 chunks(16B) = 1024 chunks, 256 threads -> 4 each
    const size_t kbase = (size_t)(e * 9 + k) * 8192;
    #pragma unroll
    for (int q = 0; q < 4; ++q) {
        int c  = tid + q * 256;
        int co = c >> 3, ch = c & 7;
        const char* src = (const char*)(g_wt + kbase + co * 64 + ch * 8);
        uint32_t dst = wbuf_s + co * XROWB + ch * 16;
        CP_ASYNC(dst, src, 16);
    }
}

__global__ __launch_bounds__(256, 1)
void moe_conv_mma(const int* __restrict__ idx, const float* __restrict__ bc,
                  float* __restrict__ out)
{
    extern __shared__ __align__(128) char smem[];
    const uint32_t sb = smem_u32(smem);

    const int g = blockIdx.x, b = blockIdx.y;      // g: 4-row group (0..15)
    const int tid = threadIdx.x;
    const int wid = tid >> 5, lane = tid & 31;
    const int mw = wid & 3, nw = wid >> 2;         // warp grid 4(m) x 2(n)
    const int h0 = g * 4;
    const int e  = idx[b];

    // ---- lane-invariant ldmatrix addressing ----
    const int row16 = (lane & 7) | ((lane >> 3) & 1) << 3;  // 0..15
    const int khalf = lane >> 4;                            // 0/1
    const int px0   = mw * 64 + row16;                      // mtile 0 pixel
    const uint32_t boff0 = (uint32_t)(nw * 64 + row16) * XROWB + khalf * 16;

    // ---- prologue: group0 = {X halo, W0}; group1 = {W1} ----
    {
        const size_t xb = ((size_t)b * HW_ * HW_) * IN_C;
        for (int c = tid; c < 396 * 8; c += 256) {
            int row = c >> 3, ch = c & 7;
            int ih = row / 66, wc = row - ih * 66;
            int gh = h0 + ih - 1, gw = wc - 1;
            int ok = ((unsigned)gh < HW_ && (unsigned)gw < HW_) ? 16 : 0;
            size_t gi = xb + ((size_t)(ok ? gh : 0) * HW_ + (ok ? gw : 0)) * IN_C + ch * 8;
            uint32_t d = (uint32_t)(row * XROWB + ch * 16);
            CP_ASYNC(sb + SM_X + d, (const char*)(g_xt + gi), ok);
        }
        load_w_tile(sb + SM_W, e, 0, tid);
        CP_COMMIT();
        load_w_tile(sb + SM_W + WSZ, e, 1, tid);
        CP_COMMIT();
    }

    // ---- acc init = bias (epilogue add folded in) ----
    const int qid = lane & 3;
    float acc[4][8][4];
    #pragma unroll
    for (int n = 0; n < 8; ++n) {
        int co = nw * 64 + n * 8 + qid * 2;
        float2 bv = __ldg((const float2*)(bc + e * OUT_C + co));
        #pragma unroll
        for (int m = 0; m < 4; ++m) {
            acc[m][n][0] = bv.x; acc[m][n][1] = bv.y;
            acc[m][n][2] = bv.x; acc[m][n][3] = bv.y;
        }
    }

    for (int k = 0; k < 9; ++k) {
        const int kh = k / 3, kw = k - kh * 3;
        const uint32_t wbuf = sb + SM_W + (k % 3) * WSZ;

        CP_WAIT1();        // W[k] (and X for k==0) landed; W[k+1] may be in flight
        __syncthreads();   // all warps done reading buf (k+2)%3 before refill
        if (k < 7) { load_w_tile(sb + SM_W + ((k + 2) % 3) * WSZ, e, k + 2, tid); CP_COMMIT(); }

        uint32_t aoff[4];
        #pragma unroll
        for (int mt = 0; mt < 4; ++mt) {
            int px = px0 + mt * 16;
            int ih = (px >> 6) + kh, wc = (px & 63) + kw;
            aoff[mt] = (uint32_t)(ih * 66 + wc) * XROWB + khalf * 16;
        }

        #pragma unroll
        for (int kc = 0; kc < 4; ++kc) {
            const uint32_t kcb = kc * 32;
            uint32_t aa[4][4], bb[4][4];
            #pragma unroll
            for (int mt = 0; mt < 4; ++mt)
                LDSM_X4(aa[mt][0], aa[mt][1], aa[mt][2], aa[mt][3], sb + SM_X + aoff[mt] + kcb);
            #pragma unroll
            for (int t = 0; t < 4; ++t)
                LDSM_X4(bb[t][0], bb[t][1], bb[t][2], bb[t][3], wbuf + boff0 + t * (16 * XROWB) + kcb);
            #pragma unroll
            for (int mt = 0; mt < 4; ++mt)
                #pragma unroll
                for (int n = 0; n < 8; ++n)
                    HMMA(acc[mt][n][0], acc[mt][n][1], acc[mt][n][2], acc[mt][n][3],
                         aa[mt][0], aa[mt][1], aa[mt][2], aa[mt][3],
                         bb[n >> 1][n & 1], bb[n >> 1][2 + (n & 1)]);
        }
        // no trailing sync: next iteration's wait+sync protects buffer reuse
    }

    // ---- epilogue: direct STG (bias already in acc) ----
    const int grp = lane >> 2;
    const size_t ob = (size_t)b * OUT_C * (HW_ * HW_) + h0 * HW_;
    #pragma unroll
    for (int mt = 0; mt < 4; ++mt) {
        int pxa = mw * 64 + mt * 16 + grp;
        #pragma unroll
        for (int n = 0; n < 8; ++n) {
            int co = nw * 64 + n * 8 + qid * 2;
            float* o0 = out + ob + (size_t)co * (HW_ * HW_);
            float* o1 = o0 + (HW_ * HW_);
            o0[pxa]     = acc[mt][n][0];
            o1[pxa]     = acc[mt][n][1];
            o0[pxa + 8] = acc[mt][n][2];
            o1[pxa + 8] = acc[mt][n][3];
        }
    }
}

// ============================================================================
extern "C" void kernel_launch(void* const* d_in, const int* in_sizes, int n_in,
                              void* d_out, int out_size)
{
    const float* x   = (const float*)d_in[0];
    const int*   idx = (const int*)  d_in[1];
    const float* Wc  = (const float*)d_in[2];
    const float* bc  = (const float*)d_in[3];
    float* out = (float*)d_out;

    static bool attr_done = false;
    if (!attr_done) {
        cudaFuncSetAttribute(moe_conv_mma, cudaFuncAttributeMaxDynamicSharedMemorySize, SMEM_SZ);
        attr_done = true;
    }

    prep_w<<<(4 * OUT_C * IN_C + 255) / 256, 256>>>(Wc);
    prep_x<<<dim3(HW_, B_), 256>>>(x);
    moe_conv_mma<<<dim3(16, B_), 256, SMEM_SZ>>>(idx, bc, out);
}

// round 15
// speedup vs baseline: 1.1000x; 1.1000x over previous
#include <cuda_runtime.h>
#include <cuda_fp16.h>
#include <cstdint>

// ============================================================================
// MoEConv implicit GEMM on mma.sync fp16 (single term, fp32 acc)
// R12: R9 shape (512thr, 16 warps, warp tile 32x64) but W staged per kernel-row
//      (3 taps / 55KB per stage, 2 buffers) -> 3 barriers instead of 9.
// x[32,64,64,64] f32, idx[32] i32, Wc[4,128,64,3,3] f32, bc[4,128] f32
// out[32,128,64,64] f32
// ============================================================================

#define HW_    64
#define B_     32
#define OUT_C  128
#define IN_C   64

// ---- device scratch (allocation-free) ----
__device__ __align__(128) __half g_xt[(size_t)B_*HW_*HW_*IN_C];  // [b][h][w][ci]
__device__ __align__(128) __half g_wt[(size_t)4*9*OUT_C*IN_C];   // [e][k][co][ci]

__device__ __forceinline__ uint32_t smem_u32(const void* p) {
    uint32_t a;
    asm("{ .reg .u64 t; cvta.to.shared.u64 t, %1; cvt.u32.u64 %0, t; }" : "=r"(a) : "l"(p));
    return a;
}

#define CP_ASYNC(dst, src, sz) \
    asm volatile("cp.async.cg.shared.global [%0], [%1], 16, %2;" :: "r"(dst), "l"(src), "r"(sz) : "memory")
#define CP_COMMIT() asm volatile("cp.async.commit_group;" ::: "memory")
#define CP_WAIT0()  asm volatile("cp.async.wait_group 0;" ::: "memory")
#define CP_WAIT1()  asm volatile("cp.async.wait_group 1;" ::: "memory")

#define LDSM_X4(r0,r1,r2,r3,a) \
    asm volatile("ldmatrix.sync.aligned.m8n8.x4.shared.b16 {%0,%1,%2,%3},[%4];" \
        : "=r"(r0),"=r"(r1),"=r"(r2),"=r"(r3) : "r"(a))

#define HMMA(c0,c1,c2,c3,a0,a1,a2,a3,b0,b1) \
    asm volatile("mma.sync.aligned.m16n8k16.row.col.f32.f16.f16.f32 " \
        "{%0,%1,%2,%3},{%4,%5,%6,%7},{%8,%9},{%0,%1,%2,%3};" \
        : "+f"(c0),"+f"(c1),"+f"(c2),"+f"(c3) \
        : "r"(a0),"r"(a1),"r"(a2),"r"(a3),"r"(b0),"r"(b1))

// ============================================================================
// Kernel 0: weights f32 -> fp16, layout [e][k][co][ci]
// ============================================================================
__global__ void prep_w(const float* __restrict__ Wc)
{
    int id = blockIdx.x * 256 + threadIdx.x;            // (e*128+co)*64+ci
    if (id >= 4 * OUT_C * IN_C) return;
    const float* src = Wc + (size_t)id * 9;
    int e   = id >> 13;
    int rem = id & 8191;
    #pragma unroll
    for (int k = 0; k < 9; ++k)
        g_wt[(size_t)(e * 9 + k) * 8192 + rem] = __float2half_rn(src[k]);
}

// ============================================================================
// Kernel 1: x [b][ci][h][w] f32 -> Xt [b][h][w][ci] fp16
// ============================================================================
__global__ void prep_x(const float* __restrict__ x)
{
    __shared__ float s[IN_C * 65];
    const int h = blockIdx.x, b = blockIdx.y, t = threadIdx.x;  // 256 threads
    {
        int ci = t >> 2, w4 = t & 3;
        const float* src = x + (((size_t)b * IN_C + ci) * HW_ + h) * HW_;
        #pragma unroll
        for (int q = 0; q < 4; ++q) {
            int w = (w4 + q * 4) * 4;
            float4 v = *(const float4*)(src + w);
            s[ci * 65 + w + 0] = v.x; s[ci * 65 + w + 1] = v.y;
            s[ci * 65 + w + 2] = v.z; s[ci * 65 + w + 3] = v.w;
        }
    }
    __syncthreads();
    {
        int w = t & 63, ci0 = (t >> 6) * 16;
        uint32_t pk[8];
        #pragma unroll
        for (int j = 0; j < 8; ++j) {
            __half h0 = __float2half_rn(s[(ci0 + 2*j    ) * 65 + w]);
            __half h1 = __float2half_rn(s[(ci0 + 2*j + 1) * 65 + w]);
            pk[j] = ((uint32_t)__half_as_ushort(h1) << 16) | __half_as_ushort(h0);
        }
        size_t base = (((size_t)b * HW_ + h) * HW_ + w) * IN_C + ci0;
        *(uint4*)(g_xt + base)     = make_uint4(pk[0], pk[1], pk[2], pk[3]);
        *(uint4*)(g_xt + base + 8) = make_uint4(pk[4], pk[5], pk[6], pk[7]);
    }
}

// ============================================================================
// Main kernel: CTA = (4 image rows = 256 px, sample). 512 threads = 16 warps
// (8m x 2n). Warp tile 32(px) x 64(co). K = 64/tap, 9 taps, fp16.
// SMEM: X halo [6][66][72 pitch] + W row-of-3-taps x2 bufs.
// Pipeline: G0={X,Wrow0}, G1={Wrow1}; kh1 prefetches Wrow2 after barrier.
// ============================================================================
#define XPITCH  72
#define XROWB   144
#define XSZ     (6 * 66 * XROWB)         // 57,024 B
#define WSZ     (OUT_C * XROWB)          // 18,432 B per tap
#define WROWSZ  (3 * WSZ)                // 55,296 B per kernel row
#define SM_X    0
#define SM_W    XSZ
#define SMEM_SZ (XSZ + 2 * WROWSZ)       // 167,616 B

__device__ __forceinline__ void load_w_row(uint32_t wbuf_s, int e, int kh, int tid)
{
    // 3 taps x 128 co x 8 chunks(16B) = 3072 chunks, 512 threads -> 6 each
    const size_t kbase = (size_t)(e * 9 + kh * 3) * 8192;
    #pragma unroll
    for (int q = 0; q < 6; ++q) {
        int c   = tid + q * 512;
        int tap = c >> 10;
        int rem = c & 1023;
        int co  = rem >> 3, ch = rem & 7;
        const char* src = (const char*)(g_wt + kbase + (size_t)tap * 8192 + co * 64 + ch * 8);
        uint32_t dst = wbuf_s + tap * WSZ + co * XROWB + ch * 16;
        CP_ASYNC(dst, src, 16);
    }
}

__global__ __launch_bounds__(512, 1)
void moe_conv_mma(const int* __restrict__ idx, const float* __restrict__ bc,
                  float* __restrict__ out)
{
    extern __shared__ __align__(128) char smem[];
    const uint32_t sb = smem_u32(smem);

    const int g = blockIdx.x, b = blockIdx.y;      // g: 4-row group (0..15)
    const int tid = threadIdx.x;
    const int wid = tid >> 5, lane = tid & 31;
    const int mw = wid & 7, nw = wid >> 3;         // warp grid 8(m) x 2(n)
    const int h0 = g * 4;
    const int e  = idx[b];

    // ---- lane-invariant ldmatrix addressing ----
    const int row16 = (lane & 7) | ((lane >> 3) & 1) << 3;  // 0..15
    const int khalf = lane >> 4;                            // 0/1
    const int px0   = mw * 32 + row16;                      // mtile 0 pixel
    const uint32_t boff0 = (uint32_t)(nw * 64 + row16) * XROWB + khalf * 16;

    // ---- prologue: G0 = {X halo, W row 0}; G1 = {W row 1} ----
    {
        const size_t xb = ((size_t)b * HW_ * HW_) * IN_C;
        for (int c = tid; c < 396 * 8; c += 512) {
            int row = c >> 3, ch = c & 7;
            int ih = row / 66, wc = row - ih * 66;
            int gh = h0 + ih - 1, gw = wc - 1;
            int ok = ((unsigned)gh < HW_ && (unsigned)gw < HW_) ? 16 : 0;
            size_t gi = xb + ((size_t)(ok ? gh : 0) * HW_ + (ok ? gw : 0)) * IN_C + ch * 8;
            uint32_t d = (uint32_t)(row * XROWB + ch * 16);
            CP_ASYNC(sb + SM_X + d, (const char*)(g_xt + gi), ok);
        }
        load_w_row(sb + SM_W, e, 0, tid);
        CP_COMMIT();
        load_w_row(sb + SM_W + WROWSZ, e, 1, tid);
        CP_COMMIT();
    }

    // ---- acc init = bias ----
    const int qid = lane & 3;
    float acc[2][8][4];
    #pragma unroll
    for (int n = 0; n < 8; ++n) {
        int co = nw * 64 + n * 8 + qid * 2;
        float2 bv = __ldg((const float2*)(bc + e * OUT_C + co));
        #pragma unroll
        for (int m = 0; m < 2; ++m) {
            acc[m][n][0] = bv.x; acc[m][n][1] = bv.y;
            acc[m][n][2] = bv.x; acc[m][n][3] = bv.y;
        }
    }

    #pragma unroll
    for (int kh = 0; kh < 3; ++kh) {
        if (kh == 0) { CP_WAIT1(); } else { CP_WAIT0(); }
        __syncthreads();   // W row kh visible to all; all warps done with other buf
        if (kh == 1) { load_w_row(sb + SM_W, e, 2, tid); CP_COMMIT(); }  // row2 -> buf0

        const uint32_t wrow = sb + SM_W + (kh & 1) * WROWSZ;  // kh=2 -> buf0

        #pragma unroll
        for (int kw = 0; kw < 3; ++kw) {
            const uint32_t wbuf = wrow + kw * WSZ;
            uint32_t aoff[2];
            #pragma unroll
            for (int mt = 0; mt < 2; ++mt) {
                int px = px0 + mt * 16;
                int ih = (px >> 6) + kh, wc = (px & 63) + kw;
                aoff[mt] = (uint32_t)(ih * 66 + wc) * XROWB + khalf * 16;
            }
            #pragma unroll
            for (int kc = 0; kc < 4; ++kc) {
                const uint32_t kcb = kc * 32;
                uint32_t aa[2][4], bb[4][4];
                #pragma unroll
                for (int mt = 0; mt < 2; ++mt)
                    LDSM_X4(aa[mt][0], aa[mt][1], aa[mt][2], aa[mt][3], sb + SM_X + aoff[mt] + kcb);
                #pragma unroll
                for (int t = 0; t < 4; ++t)
                    LDSM_X4(bb[t][0], bb[t][1], bb[t][2], bb[t][3], wbuf + boff0 + t * (16 * XROWB) + kcb);
                #pragma unroll
                for (int mt = 0; mt < 2; ++mt)
                    #pragma unroll
                    for (int n = 0; n < 8; ++n)
                        HMMA(acc[mt][n][0], acc[mt][n][1], acc[mt][n][2], acc[mt][n][3],
                             aa[mt][0], aa[mt][1], aa[mt][2], aa[mt][3],
                             bb[n >> 1][n & 1], bb[n >> 1][2 + (n & 1)]);
            }
        }
    }

    // ---- epilogue: direct STG (bias already in acc) ----
    const int grp = lane >> 2;
    const size_t ob = (size_t)b * OUT_C * (HW_ * HW_) + h0 * HW_;
    #pragma unroll
    for (int mt = 0; mt < 2; ++mt) {
        int pxa = mw * 32 + mt * 16 + grp;
        #pragma unroll
        for (int n = 0; n < 8; ++n) {
            int co = nw * 64 + n * 8 + qid * 2;
            float* o0 = out + ob + (size_t)co * (HW_ * HW_);
            float* o1 = o0 + (HW_ * HW_);
            o0[pxa]     = acc[mt][n][0];
            o1[pxa]     = acc[mt][n][1];
            o0[pxa + 8] = acc[mt][n][2];
            o1[pxa + 8] = acc[mt][n][3];
        }
    }
}

// ============================================================================
extern "C" void kernel_launch(void* const* d_in, const int* in_sizes, int n_in,
                              void* d_out, int out_size)
{
    const float* x   = (const float*)d_in[0];
    const int*   idx = (const int*)  d_in[1];
    const float* Wc  = (const float*)d_in[2];
    const float* bc  = (const float*)d_in[3];
    float* out = (float*)d_out;

    static bool attr_done = false;
    if (!attr_done) {
        cudaFuncSetAttribute(moe_conv_mma, cudaFuncAttributeMaxDynamicSharedMemorySize, SMEM_SZ);
        attr_done = true;
    }

    prep_w<<<(4 * OUT_C * IN_C + 255) / 256, 256>>>(Wc);
    prep_x<<<dim3(HW_, B_), 256>>>(x);
    moe_conv_mma<<<dim3(16, B_), 512, SMEM_SZ>>>(idx, bc, out);
}

// round 16
// speedup vs baseline: 1.1238x; 1.0217x over previous
#include <cuda_runtime.h>
#include <cuda_fp16.h>
#include <cstdint>

// ============================================================================
// MoEConv implicit GEMM on mma.sync fp16 (single term, fp32 acc)
// R16: main kernel = R15 (best). Prep fused into one launch; prep_x phase-2
//      stores made fully coalesced (quad-per-128B-line).
// x[32,64,64,64] f32, idx[32] i32, Wc[4,128,64,3,3] f32, bc[4,128] f32
// out[32,128,64,64] f32
// ============================================================================

#define HW_    64
#define B_     32
#define OUT_C  128
#define IN_C   64

// ---- device scratch (allocation-free) ----
__device__ __align__(128) __half g_xt[(size_t)B_*HW_*HW_*IN_C];  // [b][h][w][ci]
__device__ __align__(128) __half g_wt[(size_t)4*9*OUT_C*IN_C];   // [e][k][co][ci]

__device__ __forceinline__ uint32_t smem_u32(const void* p) {
    uint32_t a;
    asm("{ .reg .u64 t; cvta.to.shared.u64 t, %1; cvt.u32.u64 %0, t; }" : "=r"(a) : "l"(p));
    return a;
}

#define CP_ASYNC(dst, src, sz) \
    asm volatile("cp.async.cg.shared.global [%0], [%1], 16, %2;" :: "r"(dst), "l"(src), "r"(sz) : "memory")
#define CP_COMMIT() asm volatile("cp.async.commit_group;" ::: "memory")
#define CP_WAIT0()  asm volatile("cp.async.wait_group 0;" ::: "memory")
#define CP_WAIT1()  asm volatile("cp.async.wait_group 1;" ::: "memory")

#define LDSM_X4(r0,r1,r2,r3,a) \
    asm volatile("ldmatrix.sync.aligned.m8n8.x4.shared.b16 {%0,%1,%2,%3},[%4];" \
        : "=r"(r0),"=r"(r1),"=r"(r2),"=r"(r3) : "r"(a))

#define HMMA(c0,c1,c2,c3,a0,a1,a2,a3,b0,b1) \
    asm volatile("mma.sync.aligned.m16n8k16.row.col.f32.f16.f16.f32 " \
        "{%0,%1,%2,%3},{%4,%5,%6,%7},{%8,%9},{%0,%1,%2,%3};" \
        : "+f"(c0),"+f"(c1),"+f"(c2),"+f"(c3) \
        : "r"(a0),"r"(a1),"r"(a2),"r"(a3),"r"(b0),"r"(b1))

// ============================================================================
// Fused prep: grid (64, 33) x 256.
//   y < 32 : x [b][ci][h][w] f32 -> Xt [b][h][w][ci] fp16 (coalesced stores)
//   y == 32: weights f32 -> fp16, layout [e][k][co][ci]
// ============================================================================
__global__ void prep_all(const float* __restrict__ x, const float* __restrict__ Wc)
{
    const int t = threadIdx.x;                       // 256 threads

    if (blockIdx.y == 32) {                          // ---- weights plane ----
        #pragma unroll
        for (int q = 0; q < 2; ++q) {
            int id = blockIdx.x * 512 + q * 256 + t; // (e*128+co)*64+ci
            const float* src = Wc + (size_t)id * 9;
            int e   = id >> 13;
            int rem = id & 8191;
            #pragma unroll
            for (int k = 0; k < 9; ++k)
                g_wt[(size_t)(e * 9 + k) * 8192 + rem] = __float2half_rn(src[k]);
        }
        return;
    }

    // ---- x plane ----
    __shared__ float s[IN_C * 65];
    const int h = blockIdx.x, b = blockIdx.y;
    {
        int ci = t >> 2, w4 = t & 3;
        const float* src = x + (((size_t)b * IN_C + ci) * HW_ + h) * HW_;
        #pragma unroll
        for (int q = 0; q < 4; ++q) {
            int w = (w4 + q * 4) * 4;
            float4 v = *(const float4*)(src + w);
            s[ci * 65 + w + 0] = v.x; s[ci * 65 + w + 1] = v.y;
            s[ci * 65 + w + 2] = v.z; s[ci * 65 + w + 3] = v.w;
        }
    }
    __syncthreads();
    {
        // quad-coalesced: 4 consecutive lanes share w, cover ci 0..63 -> one
        // contiguous 128B line per quad.
        int w = t >> 2, ci0 = (t & 3) * 16;
        uint32_t pk[8];
        #pragma unroll
        for (int j = 0; j < 8; ++j) {
            __half h0 = __float2half_rn(s[(ci0 + 2*j    ) * 65 + w]);
            __half h1 = __float2half_rn(s[(ci0 + 2*j + 1) * 65 + w]);
            pk[j] = ((uint32_t)__half_as_ushort(h1) << 16) | __half_as_ushort(h0);
        }
        size_t base = (((size_t)b * HW_ + h) * HW_ + w) * IN_C + ci0;
        *(uint4*)(g_xt + base)     = make_uint4(pk[0], pk[1], pk[2], pk[3]);
        *(uint4*)(g_xt + base + 8) = make_uint4(pk[4], pk[5], pk[6], pk[7]);
    }
}

// ============================================================================
// Main kernel (unchanged from R15): CTA = (4 image rows = 256 px, sample).
// 512 threads = 16 warps (8m x 2n), warp tile 32x64. W staged per kernel-row.
// ============================================================================
#define XPITCH  72
#define XROWB   144
#define XSZ     (6 * 66 * XROWB)         // 57,024 B
#define WSZ     (OUT_C * XROWB)          // 18,432 B per tap
#define WROWSZ  (3 * WSZ)                // 55,296 B per kernel row
#define SM_X    0
#define SM_W    XSZ
#define SMEM_SZ (XSZ + 2 * WROWSZ)       // 167,616 B

__device__ __forceinline__ void load_w_row(uint32_t wbuf_s, int e, int kh, int tid)
{
    const size_t kbase = (size_t)(e * 9 + kh * 3) * 8192;
    #pragma unroll
    for (int q = 0; q < 6; ++q) {
        int c   = tid + q * 512;
        int tap = c >> 10;
        int rem = c & 1023;
        int co  = rem >> 3, ch = rem & 7;
        const char* src = (const char*)(g_wt + kbase + (size_t)tap * 8192 + co * 64 + ch * 8);
        uint32_t dst = wbuf_s + tap * WSZ + co * XROWB + ch * 16;
        CP_ASYNC(dst, src, 16);
    }
}

__global__ __launch_bounds__(512, 1)
void moe_conv_mma(const int* __restrict__ idx, const float* __restrict__ bc,
                  float* __restrict__ out)
{
    extern __shared__ __align__(128) char smem[];
    const uint32_t sb = smem_u32(smem);

    const int g = blockIdx.x, b = blockIdx.y;      // g: 4-row group (0..15)
    const int tid = threadIdx.x;
    const int wid = tid >> 5, lane = tid & 31;
    const int mw = wid & 7, nw = wid >> 3;         // warp grid 8(m) x 2(n)
    const int h0 = g * 4;
    const int e  = idx[b];

    const int row16 = (lane & 7) | ((lane >> 3) & 1) << 3;  // 0..15
    const int khalf = lane >> 4;                            // 0/1
    const int px0   = mw * 32 + row16;
    const uint32_t boff0 = (uint32_t)(nw * 64 + row16) * XROWB + khalf * 16;

    // ---- prologue: G0 = {X halo, W row 0}; G1 = {W row 1} ----
    {
        const size_t xb = ((size_t)b * HW_ * HW_) * IN_C;
        for (int c = tid; c < 396 * 8; c += 512) {
            int row = c >> 3, ch = c & 7;
            int ih = row / 66, wc = row - ih * 66;
            int gh = h0 + ih - 1, gw = wc - 1;
            int ok = ((unsigned)gh < HW_ && (unsigned)gw < HW_) ? 16 : 0;
            size_t gi = xb + ((size_t)(ok ? gh : 0) * HW_ + (ok ? gw : 0)) * IN_C + ch * 8;
            uint32_t d = (uint32_t)(row * XROWB + ch * 16);
            CP_ASYNC(sb + SM_X + d, (const char*)(g_xt + gi), ok);
        }
        load_w_row(sb + SM_W, e, 0, tid);
        CP_COMMIT();
        load_w_row(sb + SM_W + WROWSZ, e, 1, tid);
        CP_COMMIT();
    }

    // ---- acc init = bias ----
    const int qid = lane & 3;
    float acc[2][8][4];
    #pragma unroll
    for (int n = 0; n < 8; ++n) {
        int co = nw * 64 + n * 8 + qid * 2;
        float2 bv = __ldg((const float2*)(bc + e * OUT_C + co));
        #pragma unroll
        for (int m = 0; m < 2; ++m) {
            acc[m][n][0] = bv.x; acc[m][n][1] = bv.y;
            acc[m][n][2] = bv.x; acc[m][n][3] = bv.y;
        }
    }

    #pragma unroll
    for (int kh = 0; kh < 3; ++kh) {
        if (kh == 0) { CP_WAIT1(); } else { CP_WAIT0(); }
        __syncthreads();
        if (kh == 1) { load_w_row(sb + SM_W, e, 2, tid); CP_COMMIT(); }  // row2 -> buf0

        const uint32_t wrow = sb + SM_W + (kh & 1) * WROWSZ;  // kh=2 -> buf0

        #pragma unroll
        for (int kw = 0; kw < 3; ++kw) {
            const uint32_t wbuf = wrow + kw * WSZ;
            uint32_t aoff[2];
            #pragma unroll
            for (int mt = 0; mt < 2; ++mt) {
                int px = px0 + mt * 16;
                int ih = (px >> 6) + kh, wc = (px & 63) + kw;
                aoff[mt] = (uint32_t)(ih * 66 + wc) * XROWB + khalf * 16;
            }
            #pragma unroll
            for (int kc = 0; kc < 4; ++kc) {
                const uint32_t kcb = kc * 32;
                uint32_t aa[2][4], bb[4][4];
                #pragma unroll
                for (int mt = 0; mt < 2; ++mt)
                    LDSM_X4(aa[mt][0], aa[mt][1], aa[mt][2], aa[mt][3], sb + SM_X + aoff[mt] + kcb);
                #pragma unroll
                for (int t = 0; t < 4; ++t)
                    LDSM_X4(bb[t][0], bb[t][1], bb[t][2], bb[t][3], wbuf + boff0 + t * (16 * XROWB) + kcb);
                #pragma unroll
                for (int mt = 0; mt < 2; ++mt)
                    #pragma unroll
                    for (int n = 0; n < 8; ++n)
                        HMMA(acc[mt][n][0], acc[mt][n][1], acc[mt][n][2], acc[mt][n][3],
                             aa[mt][0], aa[mt][1], aa[mt][2], aa[mt][3],
                             bb[n >> 1][n & 1], bb[n >> 1][2 + (n & 1)]);
            }
        }
    }

    // ---- epilogue: direct STG (bias already in acc) ----
    const int grp = lane >> 2;
    const size_t ob = (size_t)b * OUT_C * (HW_ * HW_) + h0 * HW_;
    #pragma unroll
    for (int mt = 0; mt < 2; ++mt) {
        int pxa = mw * 32 + mt * 16 + grp;
        #pragma unroll
        for (int n = 0; n < 8; ++n) {
            int co = nw * 64 + n * 8 + qid * 2;
            float* o0 = out + ob + (size_t)co * (HW_ * HW_);
            float* o1 = o0 + (HW_ * HW_);
            o0[pxa]     = acc[mt][n][0];
            o1[pxa]     = acc[mt][n][1];
            o0[pxa + 8] = acc[mt][n][2];
            o1[pxa + 8] = acc[mt][n][3];
        }
    }
}

// ============================================================================
extern "C" void kernel_launch(void* const* d_in, const int* in_sizes, int n_in,
                              void* d_out, int out_size)
{
    const float* x   = (const float*)d_in[0];
    const int*   idx = (const int*)  d_in[1];
    const float* Wc  = (const float*)d_in[2];
    const float* bc  = (const float*)d_in[3];
    float* out = (float*)d_out;

    static bool attr_done = false;
    if (!attr_done) {
        cudaFuncSetAttribute(moe_conv_mma, cudaFuncAttributeMaxDynamicSharedMemorySize, SMEM_SZ);
        attr_done = true;
    }

    prep_all<<<dim3(HW_, B_ + 1), 256>>>(x, Wc);
    moe_conv_mma<<<dim3(16, B_), 512, SMEM_SZ>>>(idx, bc, out);
}